// round 12
// baseline (speedup 1.0000x reference)
#include <cuda_runtime.h>
#include <cuda_bf16.h>

#define POOL 7
#define NCELL 49
#define C 256

// 256 threads = 256 channels (ch = tid). All threads process cells together.
// Scalar 32-bit loads/stores: 1 wavefront per instruction -> full-rate L1
// (LDG.128's 4 wavefronts are serviced at the ~2 cyc/wf within-instr replay
// rate, which was capping L1 at ~58% in all previous rounds).
__global__ __launch_bounds__(256) void roi_align_kernel(
    const float* __restrict__ boxes,
    const float* __restrict__ meta,
    const float* __restrict__ f2,
    const float* __restrict__ f3,
    const float* __restrict__ f4,
    const float* __restrict__ f5,
    float* __restrict__ out,
    int N)
{
    const int box_id = blockIdx.x;         // 0 .. B*N-1
    const int batch  = box_id / N;
    const int tid    = threadIdx.x;

    __shared__ int4   s_off[NCELL];        // element offsets of the 4 corners
    __shared__ float2 s_frac[NCELL];       // {fx, fy}

    // --- per-box scalars (redundant per thread; cheap) ---
    const float by1 = boxes[box_id * 4 + 0];
    const float bx1 = boxes[box_id * 4 + 1];
    const float by2 = boxes[box_id * 4 + 2];
    const float bx2 = boxes[box_id * 4 + 3];

    const float area = meta[4] * meta[5];
    const float lvl  = log2f(sqrtf((by2 - by1) * (bx2 - bx1)) / (224.0f / sqrtf(area)));
    float lv = 4.0f + rintf(lvl);          // rintf = round-half-even = jnp.round
    lv = fminf(fmaxf(lv, 2.0f), 5.0f);
    const int level = (int)lv;

    int Hs;
    const float* f;
    if (level == 2)      { Hs = 256; f = f2; }
    else if (level == 3) { Hs = 128; f = f3; }
    else if (level == 4) { Hs = 64;  f = f4; }
    else                 { Hs = 32;  f = f5; }
    const int Ws = Hs;
    const float* base = f + (size_t)batch * Hs * Ws * C;

    // --- build the 49 cell descriptors (one thread per cell) ---
    if (tid < NCELL) {
        const int py = tid / POOL;
        const int px = tid - py * POOL;

        const float ys = by1 * (float)(Hs - 1)
                       + (float)py * ((by2 - by1) * (float)(Hs - 1) / (float)(POOL - 1));
        const float xs = bx1 * (float)(Ws - 1)
                       + (float)px * ((bx2 - bx1) * (float)(Ws - 1) / (float)(POOL - 1));

        const float y0f = floorf(ys);
        const float x0f = floorf(xs);
        int y0 = min(max((int)y0f, 0), Hs - 1);
        int x0 = min(max((int)x0f, 0), Ws - 1);
        const int y1 = min(y0 + 1, Hs - 1);
        const int x1 = min(x0 + 1, Ws - 1);

        s_off[tid]  = make_int4((y0 * Ws + x0) * C, (y0 * Ws + x1) * C,
                                (y1 * Ws + x0) * C, (y1 * Ws + x1) * C);
        s_frac[tid] = make_float2(xs - x0f, ys - y0f);
    }
    __syncthreads();

    // --- main loop: each thread owns one channel; scalar loads/stores ---
    const float* bch   = base + tid;                       // channel = tid
    float*       obase = out + (size_t)box_id * (NCELL * C) + tid;

    auto do_cell = [&](int cell) {
        const int4   off = s_off[cell];
        const float2 fr  = s_frac[cell];

        const float tl = __ldg(bch + off.x);   // LDG.32: 1 wavefront, coalesced
        const float tr = __ldg(bch + off.y);
        const float bl = __ldg(bch + off.z);
        const float br = __ldg(bch + off.w);

        const float top = tl + (tr - tl) * fr.x;
        const float bot = bl + (br - bl) * fr.x;
        const float o   = top + (bot - top) * fr.y;

        __stwt(obase + cell * C, o);           // STG.32 streaming: 1 wavefront
    };

    // 24 pairs + tail: two independent cells in flight (8 outstanding loads)
    #pragma unroll 1
    for (int cell = 0; cell < NCELL - 1; cell += 2) {
        do_cell(cell);
        do_cell(cell + 1);
    }
    do_cell(NCELL - 1);
}

extern "C" void kernel_launch(void* const* d_in, const int* in_sizes, int n_in,
                              void* d_out, int out_size) {
    const float* boxes = (const float*)d_in[0];
    const float* meta  = (const float*)d_in[1];
    const float* f2    = (const float*)d_in[2];
    const float* f3    = (const float*)d_in[3];
    const float* f4    = (const float*)d_in[4];
    const float* f5    = (const float*)d_in[5];
    float* out = (float*)d_out;

    const int BN = in_sizes[0] / 4;                    // total boxes = B*N
    const int B  = in_sizes[2] / (256 * 256 * 256);    // feat2 = B*256*256*C
    const int N  = BN / B;

    roi_align_kernel<<<BN, 256>>>(boxes, meta, f2, f3, f4, f5, out, N);
}

// round 13
// speedup vs baseline: 1.1333x; 1.1333x over previous
#include <cuda_runtime.h>
#include <cuda_bf16.h>
#include <cstdint>

#define POOL 7
#define NCELL 49
#define C 256
#define OUT_TILE_BYTES (NCELL * C * 4)   // 50176, 16B-aligned

__global__ __launch_bounds__(256) void roi_align_kernel(
    const float* __restrict__ boxes,
    const float* __restrict__ meta,
    const float* __restrict__ f2,
    const float* __restrict__ f3,
    const float* __restrict__ f4,
    const float* __restrict__ f5,
    float* __restrict__ out,
    int N)
{
    extern __shared__ float s_out[];       // [NCELL * C] staged output tile

    const int box_id = blockIdx.x;         // 0 .. B*N-1
    const int batch  = box_id / N;
    const int tid    = threadIdx.x;

    __shared__ int4   s_off[NCELL];        // corner element offsets
    __shared__ float2 s_frac[NCELL];       // {fx, fy}

    // --- per-box scalars (redundant per thread; cheap) ---
    const float by1 = boxes[box_id * 4 + 0];
    const float bx1 = boxes[box_id * 4 + 1];
    const float by2 = boxes[box_id * 4 + 2];
    const float bx2 = boxes[box_id * 4 + 3];

    const float area = meta[4] * meta[5];
    const float lvl  = log2f(sqrtf((by2 - by1) * (bx2 - bx1)) / (224.0f / sqrtf(area)));
    float lv = 4.0f + rintf(lvl);          // rintf = round-half-even = jnp.round
    lv = fminf(fmaxf(lv, 2.0f), 5.0f);
    const int level = (int)lv;

    int Hs;
    const float* f;
    if (level == 2)      { Hs = 256; f = f2; }
    else if (level == 3) { Hs = 128; f = f3; }
    else if (level == 4) { Hs = 64;  f = f4; }
    else                 { Hs = 32;  f = f5; }
    const int Ws = Hs;
    const float* base = f + (size_t)batch * Hs * Ws * C;

    // --- build the 49 cell descriptors (one thread per cell) ---
    if (tid < NCELL) {
        const int py = tid / POOL;
        const int px = tid - py * POOL;

        const float ys = by1 * (float)(Hs - 1)
                       + (float)py * ((by2 - by1) * (float)(Hs - 1) / (float)(POOL - 1));
        const float xs = bx1 * (float)(Ws - 1)
                       + (float)px * ((bx2 - bx1) * (float)(Ws - 1) / (float)(POOL - 1));

        const float y0f = floorf(ys);
        const float x0f = floorf(xs);
        int y0 = min(max((int)y0f, 0), Hs - 1);
        int x0 = min(max((int)x0f, 0), Ws - 1);
        const int y1 = min(y0 + 1, Hs - 1);
        const int x1 = min(x0 + 1, Ws - 1);

        s_off[tid]  = make_int4((y0 * Ws + x0) * C, (y0 * Ws + x1) * C,
                                (y1 * Ws + x0) * C, (y1 * Ws + x1) * C);
        s_frac[tid] = make_float2(xs - x0f, ys - y0f);
    }
    __syncthreads();

    // --- main loop: 64 lanes x float4 cover C=256; 4 cell-groups ---
    const int ch = (tid & 63) * 4;         // channel offset
    const int g  = tid >> 6;               // cell group 0..3
    const float* bch = base + ch;

    auto do_cell = [&](int cell) {
        const int4   off = s_off[cell];
        const float2 fr  = s_frac[cell];

        const float4 tl = *(const float4*)(bch + off.x);
        const float4 tr = *(const float4*)(bch + off.y);
        const float4 bl = *(const float4*)(bch + off.z);
        const float4 br = *(const float4*)(bch + off.w);

        float4 o;
        {
            const float top = tl.x + (tr.x - tl.x) * fr.x;
            const float bot = bl.x + (br.x - bl.x) * fr.x;
            o.x = top + (bot - top) * fr.y;
        }
        {
            const float top = tl.y + (tr.y - tl.y) * fr.x;
            const float bot = bl.y + (br.y - bl.y) * fr.x;
            o.y = top + (bot - top) * fr.y;
        }
        {
            const float top = tl.z + (tr.z - tl.z) * fr.x;
            const float bot = bl.z + (br.z - bl.z) * fr.x;
            o.z = top + (bot - top) * fr.y;
        }
        {
            const float top = tl.w + (tr.w - tl.w) * fr.x;
            const float bot = bl.w + (br.w - bl.w) * fr.x;
            o.w = top + (bot - top) * fr.y;
        }
        // STS.128 (~4 cyc/512B) instead of STG.128 (12 cyc/512B)
        *(float4*)(s_out + cell * C + ch) = o;
    };

    #pragma unroll 1
    for (int k = 0; k < 6; k++) {
        const int c0 = g + 8 * k;
        do_cell(c0);
        do_cell(c0 + 4);
    }
    if (g == 0) do_cell(48);

    __syncthreads();

    // --- one bulk TMA store: smem tile -> contiguous 50,176B output block ---
    if (tid == 0) {
        // make generic-proxy STS results visible to the async proxy
        asm volatile("fence.proxy.async.shared::cta;" ::: "memory");

        uint32_t s_addr;
        asm("{ .reg .u64 t; cvta.to.shared.u64 t, %1; cvt.u32.u64 %0, t; }"
            : "=r"(s_addr) : "l"((const void*)s_out));
        float* dst = out + (size_t)box_id * (NCELL * C);

        asm volatile(
            "cp.async.bulk.global.shared::cta.bulk_group [%0], [%1], %2;"
            :: "l"(dst), "r"(s_addr), "r"((uint32_t)OUT_TILE_BYTES)
            : "memory");
        asm volatile("cp.async.bulk.commit_group;" ::: "memory");
        asm volatile("cp.async.bulk.wait_group 0;" ::: "memory");  // keep smem live
    }
}

extern "C" void kernel_launch(void* const* d_in, const int* in_sizes, int n_in,
                              void* d_out, int out_size) {
    const float* boxes = (const float*)d_in[0];
    const float* meta  = (const float*)d_in[1];
    const float* f2    = (const float*)d_in[2];
    const float* f3    = (const float*)d_in[3];
    const float* f4    = (const float*)d_in[4];
    const float* f5    = (const float*)d_in[5];
    float* out = (float*)d_out;

    const int BN = in_sizes[0] / 4;                    // total boxes = B*N
    const int B  = in_sizes[2] / (256 * 256 * 256);    // feat2 = B*256*256*C
    const int N  = BN / B;

    cudaFuncSetAttribute(roi_align_kernel,
                         cudaFuncAttributeMaxDynamicSharedMemorySize,
                         OUT_TILE_BYTES);

    roi_align_kernel<<<BN, 256, OUT_TILE_BYTES>>>(boxes, meta, f2, f3, f4, f5, out, N);
}

// round 14
// speedup vs baseline: 1.3414x; 1.1836x over previous
#include <cuda_runtime.h>
#include <cuda_bf16.h>
#include <cstdint>

#define POOL 7
#define NCELL 49
#define C 256
#define CHUNK 8                         // cells per TMA store chunk
#define CHUNK_BYTES (CHUNK * C * 4)     // 8192
#define SMEM_FLOATS (2 * CHUNK * C)     // double buffer

__global__ __launch_bounds__(256) void roi_align_kernel(
    const float* __restrict__ boxes,
    const float* __restrict__ meta,
    const float* __restrict__ f2,
    const float* __restrict__ f3,
    const float* __restrict__ f4,
    const float* __restrict__ f5,
    float* __restrict__ out,
    int N)
{
    __shared__ float  s_out[SMEM_FLOATS];  // 16 KB: 2 x 8-cell output chunks
    __shared__ int4   s_off[NCELL];
    __shared__ float2 s_frac[NCELL];       // {fx, fy}

    const int box_id = blockIdx.x;         // 0 .. B*N-1
    const int batch  = box_id / N;
    const int tid    = threadIdx.x;

    // --- per-box scalars (redundant per thread; cheap) ---
    const float by1 = boxes[box_id * 4 + 0];
    const float bx1 = boxes[box_id * 4 + 1];
    const float by2 = boxes[box_id * 4 + 2];
    const float bx2 = boxes[box_id * 4 + 3];

    const float area = meta[4] * meta[5];
    const float lvl  = log2f(sqrtf((by2 - by1) * (bx2 - bx1)) / (224.0f / sqrtf(area)));
    float lv = 4.0f + rintf(lvl);          // rintf = round-half-even = jnp.round
    lv = fminf(fmaxf(lv, 2.0f), 5.0f);
    const int level = (int)lv;

    int Hs;
    const float* f;
    if (level == 2)      { Hs = 256; f = f2; }
    else if (level == 3) { Hs = 128; f = f3; }
    else if (level == 4) { Hs = 64;  f = f4; }
    else                 { Hs = 32;  f = f5; }
    const int Ws = Hs;
    const float* base = f + (size_t)batch * Hs * Ws * C;

    // --- build the 49 cell descriptors (one thread per cell) ---
    if (tid < NCELL) {
        const int py = tid / POOL;
        const int px = tid - py * POOL;

        const float ys = by1 * (float)(Hs - 1)
                       + (float)py * ((by2 - by1) * (float)(Hs - 1) / (float)(POOL - 1));
        const float xs = bx1 * (float)(Ws - 1)
                       + (float)px * ((bx2 - bx1) * (float)(Ws - 1) / (float)(POOL - 1));

        const float y0f = floorf(ys);
        const float x0f = floorf(xs);
        int y0 = min(max((int)y0f, 0), Hs - 1);
        int x0 = min(max((int)x0f, 0), Ws - 1);
        const int y1 = min(y0 + 1, Hs - 1);
        const int x1 = min(x0 + 1, Ws - 1);

        s_off[tid]  = make_int4((y0 * Ws + x0) * C, (y0 * Ws + x1) * C,
                                (y1 * Ws + x0) * C, (y1 * Ws + x1) * C);
        s_frac[tid] = make_float2(xs - x0f, ys - y0f);
    }
    __syncthreads();

    const int ch = (tid & 63) * 4;         // channel offset (64 lanes x float4 = C)
    const int g  = tid >> 6;               // cell group 0..3
    const float* bch = base + ch;
    float* obox = out + (size_t)box_id * (NCELL * C);

    uint32_t s_addr_base;
    asm("{ .reg .u64 t; cvta.to.shared.u64 t, %1; cvt.u32.u64 %0, t; }"
        : "=r"(s_addr_base) : "l"((const void*)s_out));

    // compute one cell into the staging buffer at chunk-local slot `slot`
    auto do_cell = [&](int cell, float* buf, int slot) {
        const int4   off = s_off[cell];
        const float2 fr  = s_frac[cell];

        const float4 tl = *(const float4*)(bch + off.x);
        const float4 tr = *(const float4*)(bch + off.y);
        const float4 bl = *(const float4*)(bch + off.z);
        const float4 br = *(const float4*)(bch + off.w);

        float4 o;
        {
            const float top = tl.x + (tr.x - tl.x) * fr.x;
            const float bot = bl.x + (br.x - bl.x) * fr.x;
            o.x = top + (bot - top) * fr.y;
        }
        {
            const float top = tl.y + (tr.y - tl.y) * fr.x;
            const float bot = bl.y + (br.y - bl.y) * fr.x;
            o.y = top + (bot - top) * fr.y;
        }
        {
            const float top = tl.z + (tr.z - tl.z) * fr.x;
            const float bot = bl.z + (br.z - bl.z) * fr.x;
            o.z = top + (bot - top) * fr.y;
        }
        {
            const float top = tl.w + (tr.w - tl.w) * fr.x;
            const float bot = bl.w + (br.w - bl.w) * fr.x;
            o.w = top + (bot - top) * fr.y;
        }
        *(float4*)(buf + slot * C + ch) = o;   // STS.128 (cheap) replaces STG.128
    };

    // 6 chunks of 8 cells, double-buffered; one bulk-async store per chunk.
    #pragma unroll 1
    for (int k = 0; k < 6; k++) {
        const int b = k & 1;
        float* buf = s_out + b * (CHUNK * C);

        if (k >= 2) {
            // ensure the store that used this buffer (chunk k-2) has read it out
            if (tid == 0)
                asm volatile("cp.async.bulk.wait_group.read 1;" ::: "memory");
            __syncthreads();
        }

        // group g computes chunk-local cells g and g+4 (global 8k+g, 8k+g+4)
        do_cell(8 * k + g,     buf, g);
        do_cell(8 * k + g + 4, buf, g + 4);
        __syncthreads();

        if (tid == 0) {
            asm volatile("fence.proxy.async.shared::cta;" ::: "memory");
            asm volatile(
                "cp.async.bulk.global.shared::cta.bulk_group [%0], [%1], %2;"
                :: "l"(obox + (size_t)(8 * k) * C),
                   "r"(s_addr_base + b * CHUNK_BYTES),
                   "r"((uint32_t)CHUNK_BYTES)
                : "memory");
            asm volatile("cp.async.bulk.commit_group;" ::: "memory");
        }
    }

    // tail: cell 48 via buffer 0 (its last store was chunk 4)
    if (tid == 0)
        asm volatile("cp.async.bulk.wait_group.read 1;" ::: "memory");
    __syncthreads();
    if (g == 0) do_cell(48, s_out, 0);
    __syncthreads();
    if (tid == 0) {
        asm volatile("fence.proxy.async.shared::cta;" ::: "memory");
        asm volatile(
            "cp.async.bulk.global.shared::cta.bulk_group [%0], [%1], %2;"
            :: "l"(obox + (size_t)48 * C), "r"(s_addr_base), "r"((uint32_t)(C * 4))
            : "memory");
        asm volatile("cp.async.bulk.commit_group;" ::: "memory");
        // smem must stay alive until all bulk stores have read it
        asm volatile("cp.async.bulk.wait_group.read 0;" ::: "memory");
    }
}

extern "C" void kernel_launch(void* const* d_in, const int* in_sizes, int n_in,
                              void* d_out, int out_size) {
    const float* boxes = (const float*)d_in[0];
    const float* meta  = (const float*)d_in[1];
    const float* f2    = (const float*)d_in[2];
    const float* f3    = (const float*)d_in[3];
    const float* f4    = (const float*)d_in[4];
    const float* f5    = (const float*)d_in[5];
    float* out = (float*)d_out;

    const int BN = in_sizes[0] / 4;                    // total boxes = B*N
    const int B  = in_sizes[2] / (256 * 256 * 256);    // feat2 = B*256*256*C
    const int N  = BN / B;

    roi_align_kernel<<<BN, 256>>>(boxes, meta, f2, f3, f4, f5, out, N);
}

// round 15
// speedup vs baseline: 1.4642x; 1.0916x over previous
#include <cuda_runtime.h>
#include <cuda_bf16.h>

#define POOL 7
#define NCELL 49
#define C 256

__global__ __launch_bounds__(256) void roi_align_kernel(
    const float* __restrict__ boxes,
    const float* __restrict__ meta,
    const float* __restrict__ f2,
    const float* __restrict__ f3,
    const float* __restrict__ f4,
    const float* __restrict__ f5,
    float* __restrict__ out,
    int N)
{
    const int box_id = blockIdx.x;         // 0 .. B*N-1
    const int batch  = box_id / N;
    const int tid    = threadIdx.x;

    // Per-cell descriptors: packed element offsets of the 4 corners + frac weights
    __shared__ int4   s_off[NCELL];
    __shared__ float2 s_frac[NCELL];       // {fx, fy}

    // --- per-box scalars (redundant per thread; cheap) ---
    const float by1 = boxes[box_id * 4 + 0];
    const float bx1 = boxes[box_id * 4 + 1];
    const float by2 = boxes[box_id * 4 + 2];
    const float bx2 = boxes[box_id * 4 + 3];

    const float area = meta[4] * meta[5];
    const float lvl  = log2f(sqrtf((by2 - by1) * (bx2 - bx1)) / (224.0f / sqrtf(area)));
    float lv = 4.0f + rintf(lvl);          // rintf = round-half-even = jnp.round
    lv = fminf(fmaxf(lv, 2.0f), 5.0f);
    const int level = (int)lv;

    int Hs;
    const float* f;
    if (level == 2)      { Hs = 256; f = f2; }
    else if (level == 3) { Hs = 128; f = f3; }
    else if (level == 4) { Hs = 64;  f = f4; }
    else                 { Hs = 32;  f = f5; }
    const int Ws = Hs;
    const float* base = f + (size_t)batch * Hs * Ws * C;

    // --- build the 49 cell descriptors (one thread per cell) ---
    if (tid < NCELL) {
        const int py = tid / POOL;
        const int px = tid - py * POOL;

        const float ys = by1 * (float)(Hs - 1)
                       + (float)py * ((by2 - by1) * (float)(Hs - 1) / (float)(POOL - 1));
        const float xs = bx1 * (float)(Ws - 1)
                       + (float)px * ((bx2 - bx1) * (float)(Ws - 1) / (float)(POOL - 1));

        const float y0f = floorf(ys);
        const float x0f = floorf(xs);
        int y0 = min(max((int)y0f, 0), Hs - 1);
        int x0 = min(max((int)x0f, 0), Ws - 1);
        const int y1 = min(y0 + 1, Hs - 1);
        const int x1 = min(x0 + 1, Ws - 1);

        s_off[tid]  = make_int4((y0 * Ws + x0) * C, (y0 * Ws + x1) * C,
                                (y1 * Ws + x0) * C, (y1 * Ws + x1) * C);
        s_frac[tid] = make_float2(xs - x0f, ys - y0f);
    }
    __syncthreads();

    // --- main loop: 64 lanes x float4 cover C=256; 4 cell-groups ---
    const int ch  = (tid & 63) * 4;        // channel offset
    const int g   = tid >> 6;              // cell group 0..3
    const int rot = (tid >> 5) % 6;        // per-warp phase skew: decorrelate
                                           // load bursts across the 8 warps so
                                           // the L1tex queue isn't flooded in
                                           // lockstep (convoy breaker)
    const float* bch   = base + ch;
    float*       obase = out + (size_t)box_id * (NCELL * C) + ch;

    auto do_cell = [&](int cell) {
        const int4   off = s_off[cell];
        const float2 fr  = s_frac[cell];

        const float4 tl = *(const float4*)(bch + off.x);
        const float4 tr = *(const float4*)(bch + off.y);
        const float4 bl = *(const float4*)(bch + off.z);
        const float4 br = *(const float4*)(bch + off.w);

        float4 o;
        {
            const float top = tl.x + (tr.x - tl.x) * fr.x;
            const float bot = bl.x + (br.x - bl.x) * fr.x;
            o.x = top + (bot - top) * fr.y;
        }
        {
            const float top = tl.y + (tr.y - tl.y) * fr.x;
            const float bot = bl.y + (br.y - bl.y) * fr.x;
            o.y = top + (bot - top) * fr.y;
        }
        {
            const float top = tl.z + (tr.z - tl.z) * fr.x;
            const float bot = bl.z + (br.z - bl.z) * fr.x;
            o.z = top + (bot - top) * fr.y;
        }
        {
            const float top = tl.w + (tr.w - tl.w) * fr.x;
            const float bot = bl.w + (br.w - bl.w) * fr.x;
            o.w = top + (bot - top) * fr.y;
        }
        __stwt((float4*)(obase + (size_t)cell * C), o);  // streaming store
    };

    // groups 0..3 cover cells g+4k; rotated start phase per warp.
    // Cell visit order is irrelevant to the output (disjoint stores).
    #pragma unroll 1
    for (int kk = 0; kk < 6; kk++) {
        int k = kk + rot;
        if (k >= 6) k -= 6;
        const int c0 = g + 8 * k;
        do_cell(c0);
        do_cell(c0 + 4);
    }
    if (g == 0) do_cell(48);
}

extern "C" void kernel_launch(void* const* d_in, const int* in_sizes, int n_in,
                              void* d_out, int out_size) {
    const float* boxes = (const float*)d_in[0];
    const float* meta  = (const float*)d_in[1];
    const float* f2    = (const float*)d_in[2];
    const float* f3    = (const float*)d_in[3];
    const float* f4    = (const float*)d_in[4];
    const float* f5    = (const float*)d_in[5];
    float* out = (float*)d_out;

    const int BN = in_sizes[0] / 4;                    // total boxes = B*N
    const int B  = in_sizes[2] / (256 * 256 * 256);    // feat2 = B*256*256*C
    const int N  = BN / B;

    roi_align_kernel<<<BN, 256>>>(boxes, meta, f2, f3, f4, f5, out, N);
}